// round 16
// baseline (speedup 1.0000x reference)
#include <cuda_runtime.h>
#include <math.h>

#define NODE_IN 64
#define NODE_OUT 96
#define EDGE_IN 32
#define EDGE_OUT 32
#define D0 128
#define DC 192
#define NCLS 2
#define MAXN 50000
#define MAXE 800000

#define NBLK 592      // 4 CTAs/SM x 148 SMs -> co-resident (grid barrier safe)
#define NTHR 256

#define APITCH 20     // A smem pitch (floats): 16B-aligned rows, conflict-free frag reads
#define BPITCH 72     // B smem pitch (floats): conflict-free

// ---------------- device scratch ----------------
__device__ int   g_deg_in[MAXN];
__device__ int   g_deg_out[MAXN];
__device__ int   g_cursor[MAXN];
__device__ int   g_off[MAXN + 1];
__device__ float g_inv_in[MAXN];
__device__ float g_inv_out[MAXN];
__device__ int   g_csr_src[MAXE];
__device__ int   g_csr_eid[MAXE];
__device__ float g_csr_w[MAXE];      // inv_out[src] precomputed at fill
__device__ float g_bufA[(size_t)MAXN * DC];
__device__ float g_bufB[(size_t)MAXN * DC];
__device__ int   g_bsum[512];
__device__ int   g_bpre[512];

__device__ int            g_bar_count;
__device__ volatile int   g_bar_gen;

// ---------------- shared memory ----------------
struct SmemU {
    union {
        struct { float As[2][128 * APITCH]; float Bs[2][16 * BPITCH]; } g;  // ~29.7 KB
        struct { int tmp[NTHR]; } s;
    };
};

// ---------------- grid-wide barrier ----------------
__device__ __forceinline__ void gsync() {
    __syncthreads();
    if (threadIdx.x == 0) {
        __threadfence();
        int gen = g_bar_gen;
        if (atomicAdd(&g_bar_count, 1) == (int)gridDim.x - 1) {
            g_bar_count = 0;
            __threadfence();
            g_bar_gen = gen + 1;
        } else {
            while (g_bar_gen == gen) { }
        }
    }
    __syncthreads();
}

__device__ __forceinline__ void cp16(float* sdst, const float* gsrc, int valid) {
    unsigned sa = (unsigned)__cvta_generic_to_shared(sdst);
    int sz = valid ? 16 : 0;
    asm volatile("cp.async.cg.shared.global [%0], [%1], 16, %2;\n"
                 :: "r"(sa), "l"(gsrc), "r"(sz));
}
__device__ __forceinline__ void cp_commit() {
    asm volatile("cp.async.commit_group;\n");
}
template <int N>
__device__ __forceinline__ void cp_wait() {
    asm volatile("cp.async.wait_group %0;\n" :: "n"(N));
}

__device__ __forceinline__ void mma_tf32(float c[4], const unsigned a[4], const unsigned b[2]) {
    asm volatile(
        "mma.sync.aligned.m16n8k8.row.col.f32.tf32.tf32.f32 "
        "{%0,%1,%2,%3}, {%4,%5,%6,%7}, {%8,%9}, {%0,%1,%2,%3};"
        : "+f"(c[0]), "+f"(c[1]), "+f"(c[2]), "+f"(c[3])
        : "r"(a[0]), "r"(a[1]), "r"(a[2]), "r"(a[3]), "r"(b[0]), "r"(b[1]));
}

// ---------------- TF32 tensor-core GEMM stage (cp.async double-buffered) -------
__device__ void gemm_stage(const float* __restrict__ A, const float* __restrict__ W,
                           const float* __restrict__ bias, float* __restrict__ C,
                           int nrows, int din, int dout, int ldc, int coff,
                           int maskdeg, SmemU* sm) {
    const int BM = 128, BN = 64, BK = 16;
    int tid = threadIdx.x;
    int w = tid >> 5, lane = tid & 31;
    int tq = lane >> 2, tr = lane & 3;
    int woff = (w & 3) * 32;
    int noff = (w >> 2) * 32;

    int tilesX = (dout + BN - 1) / BN;
    int tilesY = (nrows + BM - 1) / BM;
    int numTiles = tilesX * tilesY;

    int lar0 = (tid * 2) >> 2;
    int lak0 = ((tid * 2) & 3) * 4;
    int lar1 = (tid * 2 + 1) >> 2;
    int lak1 = ((tid * 2 + 1) & 3) * 4;
    int lbk = tid >> 4;
    int lbc = (tid & 15) * 4;

    for (int t = blockIdx.x; t < numTiles; t += gridDim.x) {
        int bx = t % tilesX, by = t / tilesX;
        int row0 = by * BM, col0 = bx * BN;
        int nt = din / BK;

        float acc[2][4][4];
        #pragma unroll
        for (int m = 0; m < 2; m++)
            #pragma unroll
            for (int j = 0; j < 4; j++)
                #pragma unroll
                for (int c = 0; c < 4; c++) acc[m][j][c] = 0.f;

        {
            int r0 = row0 + lar0, r1 = row0 + lar1;
            cp16(&sm->g.As[0][lar0 * APITCH + lak0],
                 &A[(size_t)min(r0, nrows - 1) * din + lak0], r0 < nrows);
            cp16(&sm->g.As[0][lar1 * APITCH + lak1],
                 &A[(size_t)min(r1, nrows - 1) * din + lak1], r1 < nrows);
            int cc = col0 + lbc;
            cp16(&sm->g.Bs[0][lbk * BPITCH + lbc],
                 &W[(size_t)lbk * dout + min(cc, dout - 4)], cc + 3 < dout);
            cp_commit();
        }

        for (int it = 0; it < nt; it++) {
            int cur = it & 1;
            if (it + 1 < nt) {
                int nxt = cur ^ 1;
                int kb = (it + 1) * BK;
                int r0 = row0 + lar0, r1 = row0 + lar1;
                cp16(&sm->g.As[nxt][lar0 * APITCH + lak0],
                     &A[(size_t)min(r0, nrows - 1) * din + kb + lak0], r0 < nrows);
                cp16(&sm->g.As[nxt][lar1 * APITCH + lak1],
                     &A[(size_t)min(r1, nrows - 1) * din + kb + lak1], r1 < nrows);
                int cc = col0 + lbc;
                cp16(&sm->g.Bs[nxt][(lbk)*BPITCH + lbc],
                     &W[(size_t)(kb + lbk) * dout + min(cc, dout - 4)], cc + 3 < dout);
                cp_commit();
                cp_wait<1>();
            } else {
                cp_wait<0>();
            }
            __syncthreads();

            const float* As = sm->g.As[cur];
            const float* Bs = sm->g.Bs[cur];
            #pragma unroll
            for (int kc = 0; kc < BK; kc += 8) {
                unsigned a[2][4], b[4][2];
                #pragma unroll
                for (int m = 0; m < 2; m++) {
                    int br = woff + 16 * m + tq;
                    a[m][0] = __float_as_uint(As[br * APITCH + kc + tr]);
                    a[m][1] = __float_as_uint(As[(br + 8) * APITCH + kc + tr]);
                    a[m][2] = __float_as_uint(As[br * APITCH + kc + tr + 4]);
                    a[m][3] = __float_as_uint(As[(br + 8) * APITCH + kc + tr + 4]);
                }
                #pragma unroll
                for (int j = 0; j < 4; j++) {
                    int bn = noff + 8 * j + tq;
                    b[j][0] = __float_as_uint(Bs[(kc + tr) * BPITCH + bn]);
                    b[j][1] = __float_as_uint(Bs[(kc + tr + 4) * BPITCH + bn]);
                }
                #pragma unroll
                for (int m = 0; m < 2; m++)
                    #pragma unroll
                    for (int j = 0; j < 4; j++)
                        mma_tf32(acc[m][j], a[m], b[j]);
            }
            __syncthreads();
        }

        #pragma unroll
        for (int m = 0; m < 2; m++) {
            #pragma unroll
            for (int j = 0; j < 4; j++) {
                int cg = col0 + noff + 8 * j + 2 * tr;
                if (cg >= dout) continue;
                float b0 = bias[cg], b1 = bias[cg + 1];
                int rg = row0 + woff + 16 * m + tq;
                #pragma unroll
                for (int h = 0; h < 2; h++) {
                    int r = rg + 8 * h;
                    if (r < nrows) {
                        float scale = (maskdeg && g_deg_in[r] == 0) ? 0.f : 1.f;
                        float2 v;
                        v.x = scale * fmaxf(acc[m][j][2 * h + 0] + b0, 0.f);
                        v.y = scale * fmaxf(acc[m][j][2 * h + 1] + b1, 0.f);
                        *(float2*)&C[(size_t)r * ldc + coff + cg] = v;
                    }
                }
            }
        }
    }
}

// ---------------- conv aggregation, 4-edge unroll, precomputed weights ----------------
template <int ND>
__device__ __forceinline__ void conv_agg(const float* __restrict__ H, float* __restrict__ OUT,
                                         int n, int warp_g, int warps_total, int lane) {
    const int d = ND * 32;
    for (int v = warp_g; v < n; v += warps_total) {
        int start = g_off[v], end = g_off[v + 1];
        float acc[ND];
        #pragma unroll
        for (int i = 0; i < ND; i++) acc[i] = 0.f;
        int p = start;
        for (; p + 3 < end; p += 4) {
            int s0 = g_csr_src[p],     s1 = g_csr_src[p + 1];
            int s2 = g_csr_src[p + 2], s3 = g_csr_src[p + 3];
            float w0 = g_csr_w[p],     w1 = g_csr_w[p + 1];
            float w2 = g_csr_w[p + 2], w3 = g_csr_w[p + 3];
            const float* h0 = H + (size_t)s0 * d;
            const float* h1 = H + (size_t)s1 * d;
            const float* h2 = H + (size_t)s2 * d;
            const float* h3 = H + (size_t)s3 * d;
            #pragma unroll
            for (int i = 0; i < ND; i++) {
                int k = lane + 32 * i;
                acc[i] += h0[k] * w0 + h1[k] * w1 + h2[k] * w2 + h3[k] * w3;
            }
        }
        for (; p < end; p++) {
            int s0 = g_csr_src[p];
            float w0 = g_csr_w[p];
            const float* h0 = H + (size_t)s0 * d;
            #pragma unroll
            for (int i = 0; i < ND; i++)
                acc[i] += h0[lane + 32 * i] * w0;
        }
        float wi = g_inv_in[v];
        #pragma unroll
        for (int i = 0; i < ND; i++)
            OUT[(size_t)v * d + lane + 32 * i] = acc[i] * wi;
    }
}

// ---------------- fused persistent kernel ----------------
__global__ void __launch_bounds__(NTHR, 4)
fused_gnn(const float* __restrict__ node_feats, const float* __restrict__ edge_feats,
          const float* __restrict__ Wn, const float* __restrict__ bn,
          const float* __restrict__ We, const float* __restrict__ be,
          const float* __restrict__ Wc0, const float* __restrict__ bc0,
          const float* __restrict__ Wc1, const float* __restrict__ bc1,
          const float* __restrict__ Wl0, const float* __restrict__ bl0,
          const float* __restrict__ Wo, const float* __restrict__ bo,
          const int* __restrict__ src, const int* __restrict__ dst,
          float* __restrict__ out, int n, int e) {
    __shared__ SmemU sm;
    int tid = threadIdx.x;
    int gtid = blockIdx.x * NTHR + tid;
    int gstride = gridDim.x * NTHR;
    int w = tid >> 5, lane = tid & 31;
    int warp_g = blockIdx.x * 8 + w;
    int warps_total = gridDim.x * 8;
    int nchunks = (n + NTHR - 1) / NTHR;

    // ---- 1: zero degrees ----
    for (int i = gtid; i < n; i += gstride) { g_deg_in[i] = 0; g_deg_out[i] = 0; }
    gsync();

    // ---- 2: degree histogram ----
    for (int i = gtid; i < e; i += gstride) {
        atomicAdd(&g_deg_in[dst[i]], 1);
        atomicAdd(&g_deg_out[src[i]], 1);
    }
    gsync();

    // ---- 3: inv factors + per-chunk local scan ----
    for (int i = gtid; i < n; i += gstride) {
        int di = g_deg_in[i], dn = g_deg_out[i];
        g_inv_in[i]  = rsqrtf((float)(di > 1 ? di : 1));
        g_inv_out[i] = rsqrtf((float)(dn > 1 ? dn : 1));
    }
    if ((int)blockIdx.x < nchunks) {
        int i = blockIdx.x * NTHR + tid;
        int v = (i < n) ? g_deg_in[i] : 0;
        sm.s.tmp[tid] = v;
        __syncthreads();
        for (int ofs = 1; ofs < NTHR; ofs <<= 1) {
            int cur = sm.s.tmp[tid];
            int add = (tid >= ofs) ? sm.s.tmp[tid - ofs] : 0;
            __syncthreads();
            sm.s.tmp[tid] = cur + add;
            __syncthreads();
        }
        if (i < n) g_off[i] = sm.s.tmp[tid] - v;
        if (tid == NTHR - 1) g_bsum[blockIdx.x] = sm.s.tmp[tid];
    }
    gsync();

    // ---- 4: scan block sums (one warp) ----
    if (blockIdx.x == 0 && w == 0) {
        int carry = 0;
        for (int base = 0; base < nchunks; base += 32) {
            int idx = base + lane;
            int orig = (idx < nchunks) ? g_bsum[idx] : 0;
            int v = orig;
            #pragma unroll
            for (int o = 1; o < 32; o <<= 1) {
                int t = __shfl_up_sync(0xffffffffu, v, o);
                if (lane >= o) v += t;
            }
            if (idx < nchunks) g_bpre[idx] = carry + v - orig;
            carry += __shfl_sync(0xffffffffu, v, 31);
        }
    }
    gsync();

    // ---- 5: add block prefixes ----
    for (int i = gtid; i < n; i += gstride) {
        int o = g_off[i] + g_bpre[i / NTHR];
        g_off[i] = o;
        g_cursor[i] = o;
    }
    if (gtid == 0) g_off[n] = e;
    gsync();

    // ---- 6: CSR fill (+ precompute edge weight inv_out[src]) ----
    for (int i = gtid; i < e; i += gstride) {
        int d = dst[i];
        int s = src[i];
        int p = atomicAdd(&g_cursor[d], 1);
        g_csr_src[p] = s;
        g_csr_eid[p] = i;
        g_csr_w[p]   = g_inv_out[s];
    }
    gsync();

    // ---- 7: mean edge features -> bufB[v][0..31] (stride 32), 4-edge unroll ----
    for (int v = warp_g; v < n; v += warps_total) {
        int start = g_off[v], end = g_off[v + 1];
        float acc = 0.f;
        int p = start;
        for (; p + 3 < end; p += 4) {
            int e0 = g_csr_eid[p],     e1 = g_csr_eid[p + 1];
            int e2 = g_csr_eid[p + 2], e3 = g_csr_eid[p + 3];
            acc += edge_feats[(size_t)e0 * EDGE_IN + lane]
                 + edge_feats[(size_t)e1 * EDGE_IN + lane]
                 + edge_feats[(size_t)e2 * EDGE_IN + lane]
                 + edge_feats[(size_t)e3 * EDGE_IN + lane];
        }
        for (; p < end; p++)
            acc += edge_feats[(size_t)g_csr_eid[p] * EDGE_IN + lane];
        int c = end - start;
        g_bufB[(size_t)v * EDGE_IN + lane] = (c > 0) ? acc / (float)c : 0.f;
    }
    gsync();

    // ---- 8: edge GEMM (32->32, masked) + node GEMM (64->96) -> bufA ----
    gemm_stage(g_bufB, We, be, g_bufA, n, EDGE_IN, EDGE_OUT, D0, 0, 1, &sm);
    gemm_stage(node_feats, Wn, bn, g_bufA, n, NODE_IN, NODE_OUT, D0, EDGE_OUT, 0, &sm);
    gsync();

    // ---- 9: conv0 aggregation (d=128): bufA -> bufB ----
    conv_agg<4>(g_bufA, g_bufB, n, warp_g, warps_total, lane);
    gsync();

    // ---- 10: conv0 GEMM 128->192: bufB -> bufA ----
    gemm_stage(g_bufB, Wc0, bc0, g_bufA, n, D0, DC, DC, 0, 0, &sm);
    gsync();

    // ---- 11: conv1 aggregation (d=192): bufA -> bufB ----
    conv_agg<6>(g_bufA, g_bufB, n, warp_g, warps_total, lane);
    gsync();

    // ---- 12: conv1 GEMM 192->192: bufB -> bufA ----
    gemm_stage(g_bufB, Wc1, bc1, g_bufA, n, DC, DC, DC, 0, 0, &sm);
    gsync();

    // ---- 13: linear 192->192: bufA -> bufB ----
    gemm_stage(g_bufA, Wl0, bl0, g_bufB, n, DC, DC, DC, 0, 0, &sm);
    gsync();

    // ---- 14: output head 192->2 (exact fp32) ----
    for (int v = warp_g; v < n; v += warps_total) {
        const float* hp = g_bufB + (size_t)v * DC;
        float a0 = 0.f, a1 = 0.f;
        #pragma unroll
        for (int i = 0; i < DC / 32; i++) {
            int k = lane + 32 * i;
            float h = hp[k];
            a0 += h * Wo[k * 2 + 0];
            a1 += h * Wo[k * 2 + 1];
        }
        #pragma unroll
        for (int o = 16; o; o >>= 1) {
            a0 += __shfl_xor_sync(0xffffffffu, a0, o);
            a1 += __shfl_xor_sync(0xffffffffu, a1, o);
        }
        if (lane == 0) {
            out[(size_t)v * 2 + 0] = a0 + bo[0];
            out[(size_t)v * 2 + 1] = a1 + bo[1];
        }
    }
}

// ---------------- launch: ONE kernel ----------------
extern "C" void kernel_launch(void* const* d_in, const int* in_sizes, int n_in,
                              void* d_out, int out_size) {
    const float* node_feats = (const float*)d_in[0];
    const float* edge_feats = (const float*)d_in[1];
    const float* Wn  = (const float*)d_in[2];
    const float* bn  = (const float*)d_in[3];
    const float* We  = (const float*)d_in[4];
    const float* be  = (const float*)d_in[5];
    const float* Wc0 = (const float*)d_in[6];
    const float* bc0 = (const float*)d_in[7];
    const float* Wc1 = (const float*)d_in[8];
    const float* bc1 = (const float*)d_in[9];
    const float* Wl0 = (const float*)d_in[10];
    const float* bl0 = (const float*)d_in[11];
    const float* Wo  = (const float*)d_in[12];
    const float* bo  = (const float*)d_in[13];
    const int*   src = (const int*)d_in[14];
    const int*   dst = (const int*)d_in[15];
    float* out = (float*)d_out;

    int n = in_sizes[0] / NODE_IN;   // 50000
    int e = in_sizes[14];            // 800000

    fused_gnn<<<NBLK, NTHR>>>(node_feats, edge_feats, Wn, bn, We, be,
                              Wc0, bc0, Wc1, bc1, Wl0, bl0, Wo, bo,
                              src, dst, out, n, e);
}